// round 13
// baseline (speedup 1.0000x reference)
#include <cuda_runtime.h>
#include <cuda_fp16.h>
#include <math.h>

// ---------------------------------------------------------------------------
// GaussianSplatRenderer3D — B=4, N=32768, H=W=512, k=11 (121 taps)
// Serial pipeline + PDL (programmatic dependent launch) to overlap seams:
//   zero (triggers at entry) -> splat (prologue overlaps zero tail; REDs after
//   cudaGridDependencySynchronize) -> normalize (launch overlaps splat drain).
// Splat: ONE red.global.add.noftz.v4.f16x2 per tap (REDG wavefront floor).
// ---------------------------------------------------------------------------

#define KTAP 11
#define MAXPIX (4 * 512 * 512)

static __device__ uint4 g_acc[MAXPIX];   // 8 x f16 per pixel

__global__ void zero_kernel(int npix) {
    cudaTriggerProgrammaticLaunchCompletion();   // let splat start launching
    int i = blockIdx.x * blockDim.x + threadIdx.x;
    if (i < npix)
        g_acc[i] = make_uint4(0u, 0u, 0u, 0u);
}

__global__ void __launch_bounds__(128)
splat_kernel(const float* __restrict__ pos, const float* __restrict__ cov,
             const float* __restrict__ rgb, const float* __restrict__ opa,
             const float* __restrict__ Km,  const float* __restrict__ Rm,
             const float* __restrict__ tv,  int B, int N, int H, int W)
{
    cudaTriggerProgrammaticLaunchCompletion();   // let normalize start launching

    int gid = blockIdx.x * blockDim.x + threadIdx.x;
    if (gid >= B * N) { cudaGridDependencySynchronize(); return; }
    int b = gid / N;

    const float* Kb = Km + 9 * b;
    const float* Rb = Rm + 9 * b;
    const float* tb = tv + 3 * b;

    float p0 = pos[3 * gid + 0];
    float p1 = pos[3 * gid + 1];
    float p2 = pos[3 * gid + 2];

    // Xc = R @ p + t  (mul/add chain, no FMA contraction — matches XLA dot)
    float X = __fadd_rn(__fadd_rn(__fadd_rn(__fmul_rn(Rb[0], p0), __fmul_rn(Rb[1], p1)),
                                  __fmul_rn(Rb[2], p2)), tb[0]);
    float Y = __fadd_rn(__fadd_rn(__fadd_rn(__fmul_rn(Rb[3], p0), __fmul_rn(Rb[4], p1)),
                                  __fmul_rn(Rb[5], p2)), tb[1]);
    float Z = __fadd_rn(__fadd_rn(__fadd_rn(__fmul_rn(Rb[6], p0), __fmul_rn(Rb[7], p1)),
                                  __fmul_rn(Rb[8], p2)), tb[2]);

    float zs = fmaxf(Z, 1e-6f);
    float xs = __fdiv_rn(X, zs);
    float ys = __fdiv_rn(Y, zs);

    float u = __fadd_rn(__fadd_rn(__fmul_rn(Kb[0], xs), __fmul_rn(Kb[1], ys)), Kb[2]);
    float v = __fadd_rn(__fadd_rn(__fmul_rn(Kb[3], xs), __fmul_rn(Kb[4], ys)), Kb[5]);
    float fx = Kb[0];
    float fy = Kb[4];

    float sxx = cov[3 * gid + 0];
    float syy = cov[3 * gid + 1];
    float sx = __fdiv_rn(__fmul_rn(__fsqrt_rn(fmaxf(sxx, 1e-9f)), fx), zs);
    float sy = __fdiv_rn(__fmul_rn(__fsqrt_rn(fmaxf(syy, 1e-9f)), fy), zs);

    float o  = opa[gid];
    float cr = rgb[3 * gid + 0];
    float cg = rgb[3 * gid + 1];
    float cb = rgb[3 * gid + 2];

    // Packed per-gaussian constants: slot0 scale (r,g), slot1 scale (b,z)
    __half2 h_rg = __floats2half2_rn(cr, cg);
    __half2 h_bz = __floats2half2_rn(cb, Z);

    float isx = __fdiv_rn(1.f, fmaxf(sx, 1e-6f));
    float isy = __fdiv_rn(1.f, fmaxf(sy, 1e-6f));

    // Per-axis weights (0 for OOB -> tap skipped) and byte offsets.
    // All of the above depends only on read-only inputs — overlaps zero's tail.
    float wxm[KTAP], wyo[KTAP];
    int   xoff[KTAP], yrow[KTAP];
#pragma unroll
    for (int i = 0; i < KTAP; ++i) {
        float off = (float)(i - KTAP / 2);
        float gx = __fmul_rn(off, isx);
        float gy = __fmul_rn(off, isy);
        float ewx = __expf(-0.5f * __fmul_rn(gx, gx));
        float ewy = __expf(-0.5f * __fmul_rn(gy, gy));
        int px = __float2int_rn(__fadd_rn(u, __fmul_rn(off, sx)));
        int py = __float2int_rn(__fadd_rn(v, __fmul_rn(off, sy)));
        bool okx = (px >= 0) & (px < W);
        bool oky = (py >= 0) & (py < H);
        wxm[i] = okx ? ewx : 0.f;
        wyo[i] = oky ? __fmul_rn(ewy, o) : 0.f;
        xoff[i] = px * 16;
        yrow[i] = py * W * 16;
    }

    // Wait for zero_kernel to fully complete before the first RED.
    cudaGridDependencySynchronize();

    char* baseb = (char*)g_acc + (size_t)b * (H * W) * 16;
#pragma unroll
    for (int j = 0; j < KTAP; ++j) {
        float wj = wyo[j];
        if (wj == 0.f) continue;
        char* rowp = baseb + yrow[j];
#pragma unroll
        for (int i = 0; i < KTAP; ++i) {
            float wi = wxm[i];
            if (wi == 0.f) continue;
            float a = __fmul_rn(wi, wj);
            __half2 a2 = __floats2half2_rn(a, a);
            __half2 v0 = __hmul2(h_rg, a2);   // (r*a, g*a)
            __half2 v1 = __hmul2(h_bz, a2);   // (b*a, z*a)
            unsigned r0 = *(unsigned*)&v0;
            unsigned r1 = *(unsigned*)&v1;
            unsigned r2 = *(unsigned*)&a2;    // (a, a) — free
            char* dst = rowp + xoff[i];
            asm volatile("red.global.add.noftz.v4.f16x2 [%0], {%1, %2, %3, %4};"
                         :: "l"(dst), "r"(r0), "r"(r1), "r"(r2), "r"(0u)
                         : "memory");
        }
    }
}

// x4 pixels/thread; launched with PDL — blocks come up during splat's drain,
// do index math, then wait for splat completion before reading g_acc.
__global__ void __launch_bounds__(256)
normalize_kernel(float* __restrict__ out, int B, int H, int W) {
    int HW = H * W;
    int t = blockIdx.x * blockDim.x + threadIdx.x;   // quad index
    int nquad = (B * HW) >> 2;
    if (t >= nquad) { cudaGridDependencySynchronize(); return; }
    int i0 = t << 2;

    int b   = i0 / HW;
    int pix = i0 - b * HW;
    float* rgbout = out + (size_t)b * 3 * HW + pix;
    float* zout   = out + (size_t)B * 3 * HW + (size_t)b * HW + pix;

    cudaGridDependencySynchronize();   // splat fully done + visible

    uint4 a0 = __ldcs(&g_acc[i0 + 0]);
    uint4 a1 = __ldcs(&g_acc[i0 + 1]);
    uint4 a2 = __ldcs(&g_acc[i0 + 2]);
    uint4 a3 = __ldcs(&g_acc[i0 + 3]);

    float4 r4, g4, b4, z4;
    {
        float2 f0 = __half22float2(*(__half2*)&a0.x);
        float2 f1 = __half22float2(*(__half2*)&a0.y);
        float den = fmaxf(__low2float(*(__half2*)&a0.z), 1e-6f);
        float inv; asm("rcp.approx.f32 %0, %1;" : "=f"(inv) : "f"(den));
        r4.x = f0.x * inv; g4.x = f0.y * inv; b4.x = f1.x * inv; z4.x = f1.y * inv;
    }
    {
        float2 f0 = __half22float2(*(__half2*)&a1.x);
        float2 f1 = __half22float2(*(__half2*)&a1.y);
        float den = fmaxf(__low2float(*(__half2*)&a1.z), 1e-6f);
        float inv; asm("rcp.approx.f32 %0, %1;" : "=f"(inv) : "f"(den));
        r4.y = f0.x * inv; g4.y = f0.y * inv; b4.y = f1.x * inv; z4.y = f1.y * inv;
    }
    {
        float2 f0 = __half22float2(*(__half2*)&a2.x);
        float2 f1 = __half22float2(*(__half2*)&a2.y);
        float den = fmaxf(__low2float(*(__half2*)&a2.z), 1e-6f);
        float inv; asm("rcp.approx.f32 %0, %1;" : "=f"(inv) : "f"(den));
        r4.z = f0.x * inv; g4.z = f0.y * inv; b4.z = f1.x * inv; z4.z = f1.y * inv;
    }
    {
        float2 f0 = __half22float2(*(__half2*)&a3.x);
        float2 f1 = __half22float2(*(__half2*)&a3.y);
        float den = fmaxf(__low2float(*(__half2*)&a3.z), 1e-6f);
        float inv; asm("rcp.approx.f32 %0, %1;" : "=f"(inv) : "f"(den));
        r4.w = f0.x * inv; g4.w = f0.y * inv; b4.w = f1.x * inv; z4.w = f1.y * inv;
    }

    __stcs((float4*)(rgbout),          r4);
    __stcs((float4*)(rgbout + HW),     g4);
    __stcs((float4*)(rgbout + 2 * HW), b4);
    __stcs((float4*)(zout),            z4);
}

extern "C" void kernel_launch(void* const* d_in, const int* in_sizes, int n_in,
                              void* d_out, int out_size)
{
    const float* pos = (const float*)d_in[0];
    const float* cov = (const float*)d_in[1];
    const float* rgb = (const float*)d_in[2];
    const float* opa = (const float*)d_in[3];
    const float* Km  = (const float*)d_in[4];
    const float* Rm  = (const float*)d_in[5];
    const float* tv  = (const float*)d_in[6];

    int B  = in_sizes[4] / 9;
    int N  = in_sizes[0] / (3 * B);
    int HW = out_size / (4 * B);
    int W  = (int)(sqrt((double)HW) + 0.5);
    int H  = HW / W;
    int npix = B * HW;
    int total = B * N;
    int nquad = npix >> 2;

    // zero: plain launch (head of chain)
    zero_kernel<<<(npix + 255) / 256, 256>>>(npix);

    // splat: PDL — may begin launching once zero triggers
    {
        cudaLaunchAttribute attr[1];
        attr[0].id = cudaLaunchAttributeProgrammaticStreamSerialization;
        attr[0].val.programmaticStreamSerializationAllowed = 1;
        cudaLaunchConfig_t cfg = {};
        cfg.gridDim  = dim3((total + 127) / 128);
        cfg.blockDim = dim3(128);
        cfg.attrs = attr;
        cfg.numAttrs = 1;
        cudaLaunchKernelEx(&cfg, splat_kernel, pos, cov, rgb, opa, Km, Rm, tv,
                           B, N, H, W);
    }

    // normalize: PDL — may begin launching once splat triggers
    {
        cudaLaunchAttribute attr[1];
        attr[0].id = cudaLaunchAttributeProgrammaticStreamSerialization;
        attr[0].val.programmaticStreamSerializationAllowed = 1;
        cudaLaunchConfig_t cfg = {};
        cfg.gridDim  = dim3((nquad + 255) / 256);
        cfg.blockDim = dim3(256);
        cfg.attrs = attr;
        cfg.numAttrs = 1;
        cudaLaunchKernelEx(&cfg, normalize_kernel, (float*)d_out, B, H, W);
    }
}

// round 14
// speedup vs baseline: 1.0313x; 1.0313x over previous
#include <cuda_runtime.h>
#include <cuda_fp16.h>
#include <math.h>

// ---------------------------------------------------------------------------
// GaussianSplatRenderer3D — B=4, N=32768, H=W=512, k=11 (121 taps)
// Pipeline: memset node (zero accumulator) -> splat (ONE
// red.global.add.noftz.v4.f16x2 per tap; REDG lane floor ~60us) ->
// normalize (x4 pixels/thread, rcp.approx, ldcs/stcs).
// ---------------------------------------------------------------------------

#define KTAP 11
#define MAXPIX (4 * 512 * 512)

static __device__ uint4 g_acc[MAXPIX];   // 8 x f16 per pixel

__global__ void __launch_bounds__(128)
splat_kernel(const float* __restrict__ pos, const float* __restrict__ cov,
             const float* __restrict__ rgb, const float* __restrict__ opa,
             const float* __restrict__ Km,  const float* __restrict__ Rm,
             const float* __restrict__ tv,  int B, int N, int H, int W)
{
    int gid = blockIdx.x * blockDim.x + threadIdx.x;
    if (gid >= B * N) return;
    int b = gid / N;

    const float* Kb = Km + 9 * b;
    const float* Rb = Rm + 9 * b;
    const float* tb = tv + 3 * b;

    float p0 = pos[3 * gid + 0];
    float p1 = pos[3 * gid + 1];
    float p2 = pos[3 * gid + 2];

    // Xc = R @ p + t  (mul/add chain, no FMA contraction — matches XLA dot)
    float X = __fadd_rn(__fadd_rn(__fadd_rn(__fmul_rn(Rb[0], p0), __fmul_rn(Rb[1], p1)),
                                  __fmul_rn(Rb[2], p2)), tb[0]);
    float Y = __fadd_rn(__fadd_rn(__fadd_rn(__fmul_rn(Rb[3], p0), __fmul_rn(Rb[4], p1)),
                                  __fmul_rn(Rb[5], p2)), tb[1]);
    float Z = __fadd_rn(__fadd_rn(__fadd_rn(__fmul_rn(Rb[6], p0), __fmul_rn(Rb[7], p1)),
                                  __fmul_rn(Rb[8], p2)), tb[2]);

    float zs = fmaxf(Z, 1e-6f);
    float xs = __fdiv_rn(X, zs);
    float ys = __fdiv_rn(Y, zs);

    float u = __fadd_rn(__fadd_rn(__fmul_rn(Kb[0], xs), __fmul_rn(Kb[1], ys)), Kb[2]);
    float v = __fadd_rn(__fadd_rn(__fmul_rn(Kb[3], xs), __fmul_rn(Kb[4], ys)), Kb[5]);
    float fx = Kb[0];
    float fy = Kb[4];

    float sxx = cov[3 * gid + 0];
    float syy = cov[3 * gid + 1];
    float sx = __fdiv_rn(__fmul_rn(__fsqrt_rn(fmaxf(sxx, 1e-9f)), fx), zs);
    float sy = __fdiv_rn(__fmul_rn(__fsqrt_rn(fmaxf(syy, 1e-9f)), fy), zs);

    float o  = opa[gid];
    float cr = rgb[3 * gid + 0];
    float cg = rgb[3 * gid + 1];
    float cb = rgb[3 * gid + 2];

    // Packed per-gaussian constants: slot0 scale (r,g), slot1 scale (b,z)
    __half2 h_rg = __floats2half2_rn(cr, cg);
    __half2 h_bz = __floats2half2_rn(cb, Z);

    float isx = __fdiv_rn(1.f, fmaxf(sx, 1e-6f));
    float isy = __fdiv_rn(1.f, fmaxf(sy, 1e-6f));

    // Per-axis weights (0 for OOB -> tap skipped) and byte offsets
    float wxm[KTAP], wyo[KTAP];
    int   xoff[KTAP], yrow[KTAP];
#pragma unroll
    for (int i = 0; i < KTAP; ++i) {
        float off = (float)(i - KTAP / 2);
        float gx = __fmul_rn(off, isx);
        float gy = __fmul_rn(off, isy);
        float ewx = __expf(-0.5f * __fmul_rn(gx, gx));
        float ewy = __expf(-0.5f * __fmul_rn(gy, gy));
        int px = __float2int_rn(__fadd_rn(u, __fmul_rn(off, sx)));
        int py = __float2int_rn(__fadd_rn(v, __fmul_rn(off, sy)));
        bool okx = (px >= 0) & (px < W);
        bool oky = (py >= 0) & (py < H);
        wxm[i] = okx ? ewx : 0.f;
        wyo[i] = oky ? __fmul_rn(ewy, o) : 0.f;
        xoff[i] = px * 16;
        yrow[i] = py * W * 16;
    }

    char* baseb = (char*)g_acc + (size_t)b * (H * W) * 16;
#pragma unroll
    for (int j = 0; j < KTAP; ++j) {
        float wj = wyo[j];
        if (wj == 0.f) continue;
        char* rowp = baseb + yrow[j];
#pragma unroll
        for (int i = 0; i < KTAP; ++i) {
            float wi = wxm[i];
            if (wi == 0.f) continue;
            float a = __fmul_rn(wi, wj);
            __half2 a2 = __floats2half2_rn(a, a);
            __half2 v0 = __hmul2(h_rg, a2);   // (r*a, g*a)
            __half2 v1 = __hmul2(h_bz, a2);   // (b*a, z*a)
            unsigned r0 = *(unsigned*)&v0;
            unsigned r1 = *(unsigned*)&v1;
            unsigned r2 = *(unsigned*)&a2;    // (a, a) — free
            char* dst = rowp + xoff[i];
            asm volatile("red.global.add.noftz.v4.f16x2 [%0], {%1, %2, %3, %4};"
                         :: "l"(dst), "r"(r0), "r"(r1), "r"(r2), "r"(0u)
                         : "memory");
        }
    }
}

// x4 pixels/thread; streaming loads of the dead accumulator, streaming
// stores of the write-once output; rcp.approx for the divide.
__global__ void __launch_bounds__(256)
normalize_kernel(float* __restrict__ out, int B, int H, int W) {
    int HW = H * W;
    int t = blockIdx.x * blockDim.x + threadIdx.x;   // quad index
    int nquad = (B * HW) >> 2;
    if (t >= nquad) return;
    int i0 = t << 2;

    uint4 a0 = __ldcs(&g_acc[i0 + 0]);
    uint4 a1 = __ldcs(&g_acc[i0 + 1]);
    uint4 a2 = __ldcs(&g_acc[i0 + 2]);
    uint4 a3 = __ldcs(&g_acc[i0 + 3]);

    int b   = i0 / HW;
    int pix = i0 - b * HW;

    float4 r4, g4, b4, z4;
    {
        float2 f0 = __half22float2(*(__half2*)&a0.x);
        float2 f1 = __half22float2(*(__half2*)&a0.y);
        float den = fmaxf(__low2float(*(__half2*)&a0.z), 1e-6f);
        float inv; asm("rcp.approx.f32 %0, %1;" : "=f"(inv) : "f"(den));
        r4.x = f0.x * inv; g4.x = f0.y * inv; b4.x = f1.x * inv; z4.x = f1.y * inv;
    }
    {
        float2 f0 = __half22float2(*(__half2*)&a1.x);
        float2 f1 = __half22float2(*(__half2*)&a1.y);
        float den = fmaxf(__low2float(*(__half2*)&a1.z), 1e-6f);
        float inv; asm("rcp.approx.f32 %0, %1;" : "=f"(inv) : "f"(den));
        r4.y = f0.x * inv; g4.y = f0.y * inv; b4.y = f1.x * inv; z4.y = f1.y * inv;
    }
    {
        float2 f0 = __half22float2(*(__half2*)&a2.x);
        float2 f1 = __half22float2(*(__half2*)&a2.y);
        float den = fmaxf(__low2float(*(__half2*)&a2.z), 1e-6f);
        float inv; asm("rcp.approx.f32 %0, %1;" : "=f"(inv) : "f"(den));
        r4.z = f0.x * inv; g4.z = f0.y * inv; b4.z = f1.x * inv; z4.z = f1.y * inv;
    }
    {
        float2 f0 = __half22float2(*(__half2*)&a3.x);
        float2 f1 = __half22float2(*(__half2*)&a3.y);
        float den = fmaxf(__low2float(*(__half2*)&a3.z), 1e-6f);
        float inv; asm("rcp.approx.f32 %0, %1;" : "=f"(inv) : "f"(den));
        r4.w = f0.x * inv; g4.w = f0.y * inv; b4.w = f1.x * inv; z4.w = f1.y * inv;
    }

    float* rgbout = out + (size_t)b * 3 * HW + pix;
    __stcs((float4*)(rgbout),          r4);
    __stcs((float4*)(rgbout + HW),     g4);
    __stcs((float4*)(rgbout + 2 * HW), b4);
    __stcs((float4*)(out + (size_t)B * 3 * HW + (size_t)b * HW + pix), z4);
}

extern "C" void kernel_launch(void* const* d_in, const int* in_sizes, int n_in,
                              void* d_out, int out_size)
{
    const float* pos = (const float*)d_in[0];
    const float* cov = (const float*)d_in[1];
    const float* rgb = (const float*)d_in[2];
    const float* opa = (const float*)d_in[3];
    const float* Km  = (const float*)d_in[4];
    const float* Rm  = (const float*)d_in[5];
    const float* tv  = (const float*)d_in[6];

    int B  = in_sizes[4] / 9;
    int N  = in_sizes[0] / (3 * B);
    int HW = out_size / (4 * B);
    int W  = (int)(sqrt((double)HW) + 0.5);
    int H  = HW / W;
    int npix = B * HW;

    // Zero the accumulator with a memset node (driver-optimized; no allocation).
    void* accptr = 0;
    cudaGetSymbolAddress(&accptr, g_acc);
    cudaMemsetAsync(accptr, 0, (size_t)npix * sizeof(uint4), 0);

    int total = B * N;
    splat_kernel<<<(total + 127) / 128, 128>>>(pos, cov, rgb, opa, Km, Rm, tv, B, N, H, W);

    int nquad = npix >> 2;
    normalize_kernel<<<(nquad + 255) / 256, 256>>>((float*)d_out, B, H, W);
}